// round 6
// baseline (speedup 1.0000x reference)
#include <cuda_runtime.h>
#include <cstdint>
#include <cstddef>

// Problem constants
#define B_  256
#define T_  512
#define I_  64
#define H_  256
#define G_  1024            // 4*H
#define BT_ (B_ * T_)       // 131072

// -------- scratch (device globals; no allocation allowed) --------
__device__ float g_xp[(size_t)BT_ * G_];   // gate pre-activations for current layer
__device__ float g_s0[(size_t)BT_ * H_];   // layer output sequence (ping)
__device__ float g_s1[(size_t)BT_ * H_];   // layer output sequence (pong)

// ---------------- packed f32x2 helpers (PTX-only path) ----------------
__device__ __forceinline__ unsigned long long pack2(float lo, float hi) {
    unsigned long long r;
    asm("mov.b64 %0, {%1, %2};" : "=l"(r)
        : "r"(__float_as_uint(lo)), "r"(__float_as_uint(hi)));
    return r;
}
__device__ __forceinline__ void fma2(unsigned long long& d,
                                     unsigned long long a, unsigned long long b) {
    asm("fma.rn.f32x2 %0, %1, %2, %0;" : "+l"(d) : "l"(a), "l"(b));
}
__device__ __forceinline__ float2 unpack2(unsigned long long v) {
    unsigned lo, hi;
    asm("mov.b64 {%0, %1}, %2;" : "=r"(lo), "=r"(hi) : "l"(v));
    return make_float2(__uint_as_float(lo), __uint_as_float(hi));
}
__device__ __forceinline__ unsigned long long add2(unsigned long long a,
                                                   unsigned long long b) {
    unsigned long long r;
    asm("add.rn.f32x2 %0, %1, %2;" : "=l"(r) : "l"(a), "l"(b));
    return r;
}
__device__ __forceinline__ unsigned long long shflx64(unsigned long long v, int m) {
    unsigned lo, hi;
    asm("mov.b64 {%0, %1}, %2;" : "=r"(lo), "=r"(hi) : "l"(v));
    lo = __shfl_xor_sync(0xffffffffu, lo, m);
    hi = __shfl_xor_sync(0xffffffffu, hi, m);
    unsigned long long r;
    asm("mov.b64 %0, {%1, %2};" : "=l"(r) : "r"(lo), "r"(hi));
    return r;
}

// =====================================================================
// GEMM: C[M,N] = A[M,K] * B[N,K]^T + bias1[N] (+ bias2[N])
// BM=128, BN=64, BK=16, 256 threads. f32x2 over M-pairs.
// (unchanged from the R3-passing version)
// =====================================================================
__global__ void __launch_bounds__(256, 2)
gemm_abt_bias(const float* __restrict__ A, const float* __restrict__ Bm,
              const float* __restrict__ bias1, const float* __restrict__ bias2,
              float* __restrict__ C, int M, int N, int K)
{
    __shared__ float As[16][128];
    __shared__ float Bs[16][64];

    const int tid = threadIdx.x;
    const int m0  = blockIdx.y * 128;
    const int n0  = blockIdx.x * 64;
    const int ty8 = (tid >> 4) * 8;
    const int tx4 = (tid & 15) * 4;

    unsigned long long acc2[4][4];
#pragma unroll
    for (int p = 0; p < 4; ++p)
#pragma unroll
        for (int j = 0; j < 4; ++j) acc2[p][j] = 0ULL;

    const int ntile = K >> 4;
    for (int kt = 0; kt < ntile; ++kt) {
        const int k0 = kt << 4;
#pragma unroll
        for (int r = 0; r < 2; ++r) {
            int idx = tid + (r << 8);
            int m = idx >> 2, kq = idx & 3;
            float4 v = *(const float4*)&A[(size_t)(m0 + m) * K + k0 + (kq << 2)];
            As[kq * 4 + 0][m] = v.x; As[kq * 4 + 1][m] = v.y;
            As[kq * 4 + 2][m] = v.z; As[kq * 4 + 3][m] = v.w;
        }
        {
            int n = tid >> 2, kq = tid & 3;
            float4 v = *(const float4*)&Bm[(size_t)(n0 + n) * K + k0 + (kq << 2)];
            Bs[kq * 4 + 0][n] = v.x; Bs[kq * 4 + 1][n] = v.y;
            Bs[kq * 4 + 2][n] = v.z; Bs[kq * 4 + 3][n] = v.w;
        }
        __syncthreads();

#pragma unroll
        for (int kk = 0; kk < 16; ++kk) {
            ulonglong2 a01 = *(const ulonglong2*)&As[kk][ty8];
            ulonglong2 a23 = *(const ulonglong2*)&As[kk][ty8 + 4];
            float4 bv = *(const float4*)&Bs[kk][tx4];
            unsigned long long am[4] = {a01.x, a01.y, a23.x, a23.y};
            float br[4] = {bv.x, bv.y, bv.z, bv.w};
#pragma unroll
            for (int j = 0; j < 4; ++j) {
                unsigned long long bp = pack2(br[j], br[j]);
#pragma unroll
                for (int p = 0; p < 4; ++p) fma2(acc2[p][j], am[p], bp);
            }
        }
        __syncthreads();
    }

    float bvv[4];
#pragma unroll
    for (int j = 0; j < 4; ++j) {
        float b = bias1[n0 + tx4 + j];
        if (bias2) b += bias2[n0 + tx4 + j];
        bvv[j] = b;
    }
#pragma unroll
    for (int p = 0; p < 4; ++p) {
        float4 o0, o1;
        float2 u0 = unpack2(acc2[p][0]);
        float2 u1 = unpack2(acc2[p][1]);
        float2 u2 = unpack2(acc2[p][2]);
        float2 u3 = unpack2(acc2[p][3]);
        o0.x = u0.x + bvv[0]; o0.y = u1.x + bvv[1]; o0.z = u2.x + bvv[2]; o0.w = u3.x + bvv[3];
        o1.x = u0.y + bvv[0]; o1.y = u1.y + bvv[1]; o1.z = u2.y + bvv[2]; o1.w = u3.y + bvv[3];
        *(float4*)&C[(size_t)(m0 + ty8 + 2 * p)     * N + n0 + tx4] = o0;
        *(float4*)&C[(size_t)(m0 + ty8 + 2 * p + 1) * N + n0 + tx4] = o1;
    }
}

// =====================================================================
// Recurrent LSTM scan v4: R=4 rows/thread (row-pair-packed W in regs),
// k over 8 interleaved lane-groups, h scalar-broadcast LDS.32,
// *** batch processed in chunks of 4 to bound live registers ***.
//   grid = 128 CTAs = 16 clusters x 8; cluster owns 16 batch rows.
//   CTA rank owns CTA-local gate rows [0,128): r -> gate g=r>>5, col c=r&31,
//   global row gr = g*256 + rank*32 + c.
//   Thread tid: rg = tid>>3 (4 rows r0=rg*4..+3), kg = tid&7
//   (k = jj*8+kg). rW[2][32] u64 = row-pairs (r0,r0+1),(r0+2,r0+3).
//   Per batch-chunk (4 batches): acc[2][4]; per (jj,b): 1 LDS.32
//   (conflict-free: lanes span kg, 4-way broadcast over rg) + pack2 +
//   2 FMA2. Reduce over kg (3x shfl_xor+add2), kg==0 writes STS.64 to ex.
//   Epilogue: thread -> 2 (b,c), gates register-local, coalesced h store,
//   cluster barrier (release/acquire of h via global).
// =====================================================================
#define PB 260   // hS pitch (floats)
#define PE 132   // ex pitch (floats)

__device__ __forceinline__ float fsig(float x) {
    x = fminf(fmaxf(x, -30.f), 30.f);
    return __fdividef(1.f, 1.f + __expf(-x));
}
__device__ __forceinline__ float ftanh_(float x) {
    x = fminf(fmaxf(x, -15.f), 15.f);
    float e = __expf(-2.f * x);
    return __fdividef(1.f - e, 1.f + e);
}

__global__ void __cluster_dims__(8, 1, 1) __launch_bounds__(256, 1)
lstm_rec(const float* __restrict__ Whh, const float* __restrict__ xpg,
         float* __restrict__ seq_out)
{
    __shared__ float hS[16 * PB];    // h_{t-1}: [batch][k]
    __shared__ float ex[16 * PE];    // dots: [batch][CTA-local row]

    const int tid  = threadIdx.x;
    const int rank = blockIdx.x & 7;
    const int b0   = (blockIdx.x >> 3) * 16;

    const int kg = tid & 7;          // k-interleave group
    const int rg = tid >> 3;         // rowgroup 0..31
    const int r0 = rg << 2;          // first of 4 CTA-local rows

    // W slice into registers: row-pairs packed, k = jj*8 + kg
    unsigned long long rW[2][32];
#pragma unroll
    for (int rp = 0; rp < 2; ++rp) {
        int rA = r0 + 2 * rp;
        int grA = ((rA >> 5) << 8) + (rank << 5) + (rA & 31);
#pragma unroll
        for (int jj = 0; jj < 32; ++jj) {
            int k = (jj << 3) + kg;
            rW[rp][jj] = pack2(__ldg(&Whh[(size_t)grA * H_ + k]),
                               __ldg(&Whh[(size_t)(grA + 1) * H_ + k]));
        }
    }

    // zero h buffer (t=0 state)
    for (int idx = tid; idx < 16 * PB; idx += 256) hS[idx] = 0.f;

    // epilogue mapping (t-invariant): idx = b*32 + c
    int gb[2], gc[2];
#pragma unroll
    for (int u = 0; u < 2; ++u) {
        int idx = tid + (u << 8);
        gb[u] = idx >> 5; gc[u] = idx & 31;
    }
    float cst[2] = {0.f, 0.f};

    __syncthreads();

    for (int t = 0; t < T_; ++t) {
        // ---- stage h_{t-1}: coalesced LDG.128 -> conflict-free STS.128 ----
        if (t > 0) {
#pragma unroll
            for (int jj2 = 0; jj2 < 4; ++jj2) {
                int f = tid + (jj2 << 8);
                int b = f >> 6, k0 = (f & 63) << 2;
                float4 v = *(const float4*)&seq_out[((size_t)(b0 + b) * T_ + (t - 1)) * H_ + k0];
                *(float4*)&hS[b * PB + k0] = v;
            }
        }
        // prefetch xp for this step (independent of h)
        float xv[2][4];
#pragma unroll
        for (int u = 0; u < 2; ++u)
#pragma unroll
            for (int g = 0; g < 4; ++g)
                xv[u][g] = __ldg(&xpg[((size_t)(b0 + gb[u]) * T_ + t) * G_ +
                                      (g << 8) + (rank << 5) + gc[u]]);
        __syncthreads();

        // ---- dot in 4 batch-chunks of 4 (bounds live registers) ----
        const float* hp = hS + kg;
#pragma unroll
        for (int bc = 0; bc < 4; ++bc) {
            unsigned long long acc[2][4];
#pragma unroll
            for (int b = 0; b < 4; ++b) { acc[0][b] = 0ULL; acc[1][b] = 0ULL; }

#pragma unroll
            for (int jj = 0; jj < 32; ++jj) {
                const int ko = jj << 3;
#pragma unroll
                for (int b = 0; b < 4; ++b) {
                    float hv = hp[((bc << 2) + b) * PB + ko];
                    unsigned long long h2 = pack2(hv, hv);
                    fma2(acc[0][b], rW[0][jj], h2);
                    fma2(acc[1][b], rW[1][jj], h2);
                }
            }

            // reduce over 8 kg groups: 3 packed shuffle-add stages
#pragma unroll
            for (int st = 1; st <= 4; st <<= 1) {
#pragma unroll
                for (int b = 0; b < 4; ++b) {
                    acc[0][b] = add2(acc[0][b], shflx64(acc[0][b], st));
                    acc[1][b] = add2(acc[1][b], shflx64(acc[1][b], st));
                }
            }
            if (kg == 0) {
#pragma unroll
                for (int b = 0; b < 4; ++b) {
                    *(unsigned long long*)&ex[((bc << 2) + b) * PE + r0]     = acc[0][b];
                    *(unsigned long long*)&ex[((bc << 2) + b) * PE + r0 + 2] = acc[1][b];
                }
            }
        }
        __syncthreads();

        // ---- gates + state update + h write ----
#pragma unroll
        for (int u = 0; u < 2; ++u) {
            int b = gb[u], c = gc[u];
            float iv = ex[b * PE + c]      + xv[u][0];
            float fv = ex[b * PE + 32 + c] + xv[u][1];
            float gv = ex[b * PE + 64 + c] + xv[u][2];
            float ov = ex[b * PE + 96 + c] + xv[u][3];
            float ig = fsig(iv), fg = fsig(fv), gg = ftanh_(gv), og = fsig(ov);
            cst[u] = fg * cst[u] + ig * gg;
            seq_out[((size_t)(b0 + b) * T_ + t) * H_ + (rank << 5) + c] = og * ftanh_(cst[u]);
        }

        // ---- cluster barrier: release h writes / acquire peers' ----
        asm volatile("barrier.cluster.arrive.aligned;\n\t"
                     "barrier.cluster.wait.aligned;\n\t" ::: "memory");
    }
}

// =====================================================================
// Launcher
// =====================================================================
extern "C" void kernel_launch(void* const* d_in, const int* in_sizes, int n_in,
                              void* d_out, int out_size)
{
    const float* x     = (const float*)d_in[0];
    const float* eWih0 = (const float*)d_in[1];
    const float* eWhh0 = (const float*)d_in[2];
    const float* ebih0 = (const float*)d_in[3];
    const float* ebhh0 = (const float*)d_in[4];
    const float* eWih1 = (const float*)d_in[5];
    const float* eWhh1 = (const float*)d_in[6];
    const float* ebih1 = (const float*)d_in[7];
    const float* ebhh1 = (const float*)d_in[8];
    const float* dWih0 = (const float*)d_in[9];
    const float* dWhh0 = (const float*)d_in[10];
    const float* dbih0 = (const float*)d_in[11];
    const float* dbhh0 = (const float*)d_in[12];
    const float* dWih1 = (const float*)d_in[13];
    const float* dWhh1 = (const float*)d_in[14];
    const float* dbih1 = (const float*)d_in[15];
    const float* dbhh1 = (const float*)d_in[16];
    const float* out_W = (const float*)d_in[17];
    const float* out_b = (const float*)d_in[18];
    float* out = (float*)d_out;

    void* p;
    cudaGetSymbolAddress(&p, g_xp); float* xp = (float*)p;
    cudaGetSymbolAddress(&p, g_s0); float* s0 = (float*)p;
    cudaGetSymbolAddress(&p, g_s1); float* s1 = (float*)p;

    dim3 blk(256);
    dim3 gXP(G_ / 64, BT_ / 128);   // N=1024 tiles x M tiles
    dim3 gPR(I_ / 64, BT_ / 128);   // projection N=64

    // encoder layer 0 (K = I = 64)
    gemm_abt_bias<<<gXP, blk>>>(x, eWih0, ebih0, ebhh0, xp, BT_, G_, I_);
    lstm_rec<<<128, blk>>>(eWhh0, xp, s0);
    // encoder layer 1 (K = H)
    gemm_abt_bias<<<gXP, blk>>>(s0, eWih1, ebih1, ebhh1, xp, BT_, G_, H_);
    lstm_rec<<<128, blk>>>(eWhh1, xp, s1);
    // decoder layer 0
    gemm_abt_bias<<<gXP, blk>>>(s1, dWih0, dbih0, dbhh0, xp, BT_, G_, H_);
    lstm_rec<<<128, blk>>>(dWhh0, xp, s0);
    // decoder layer 1
    gemm_abt_bias<<<gXP, blk>>>(s0, dWih1, dbih1, dbhh1, xp, BT_, G_, H_);
    lstm_rec<<<128, blk>>>(dWhh1, xp, s1);
    // output projection (N = I = 64, K = H)
    gemm_abt_bias<<<gPR, blk>>>(s1, out_W, out_b, nullptr, out, BT_, I_, H_);
}